// round 3
// baseline (speedup 1.0000x reference)
#include <cuda_runtime.h>
#include <cuda_bf16.h>
#include <cstdint>

// Problem constants (fixed by the reference setup)
#define B_DIM 4
#define N_DIM 2048
#define K_DIM 4096
#define M_DIM 4096
#define NNZ_PER_ROW 409

// Scratch for transposed x: [B, K, N] fp32 = 4*4096*2048*4 = 128 MB.
// __device__ global = the sanctioned no-alloc scratch mechanism.
__device__ float g_xt[(size_t)B_DIM * K_DIM * N_DIM];

// ---------------------------------------------------------------------------
// Kernel 1: transpose x [B, N, K] -> xt [B, K, N]
// block (32, 8), grid (K/32, N/32, B). Coalesced read along k, coalesced
// write along n, 32x33 smem tile to kill bank conflicts.
// ---------------------------------------------------------------------------
__global__ void transpose_xk(const float* __restrict__ x) {
    __shared__ float tile[32][33];
    const int b  = blockIdx.z;
    const int k0 = blockIdx.x * 32;
    const int n0 = blockIdx.y * 32;
    const int tx = threadIdx.x;
    const int ty = threadIdx.y;

    const float* xb = x + (size_t)b * N_DIM * K_DIM;
#pragma unroll
    for (int i = 0; i < 32; i += 8) {
        tile[ty + i][tx] = xb[(size_t)(n0 + ty + i) * K_DIM + (k0 + tx)];
    }
    __syncthreads();

    float* xtb = g_xt + (size_t)b * K_DIM * N_DIM;
#pragma unroll
    for (int i = 0; i < 32; i += 8) {
        xtb[(size_t)(k0 + ty + i) * N_DIM + (n0 + tx)] = tile[tx][ty + i];
    }
}

// ---------------------------------------------------------------------------
// Kernel 2: CSR SpMM on transposed activations.
// out[b, m, n] = sum_j vals[row m, j] * xt[b, cols[j], n]
//
// CTA: one sparse row m, one 1024-wide n tile, one batch b.
// 256 threads, each owns a float4 of n. Row metadata staged in smem and
// broadcast. Inner loop unrolled x8 -> 8 independent LDG.128 in flight per
// thread to cover L2 latency (~250 cyc). gridDim.z = b (slowest) keeps the
// 32 MB per-batch xt slice L2-resident so gathers are L2 hits.
// ---------------------------------------------------------------------------
__global__ void __launch_bounds__(256) csr_spmm(
    const float* __restrict__ values,
    const int*   __restrict__ row_offsets,
    const int*   __restrict__ column_indices,
    float*       __restrict__ out)
{
    __shared__ float sv[NNZ_PER_ROW + 15];
    __shared__ int   sc[NNZ_PER_ROW + 15];

    const int m   = blockIdx.y;
    const int b   = blockIdx.z;
    const int tid = threadIdx.x;
    const int n0  = blockIdx.x * 1024 + tid * 4;

    const int start = row_offsets[m];
    const int end   = row_offsets[m + 1];
    const int cnt   = end - start;

    for (int i = tid; i < cnt; i += 256) {
        sv[i] = values[start + i];
        sc[i] = column_indices[start + i];
    }
    __syncthreads();

    const float* __restrict__ xb = g_xt + (size_t)b * K_DIM * N_DIM + n0;

    float4 acc = make_float4(0.f, 0.f, 0.f, 0.f);

    int j = 0;
    for (; j + 8 <= cnt; j += 8) {
        float4 xv[8];
        float  wv[8];
#pragma unroll
        for (int u = 0; u < 8; ++u) {
            const int c = sc[j + u];
            wv[u] = sv[j + u];
            xv[u] = *reinterpret_cast<const float4*>(xb + (size_t)c * N_DIM);
        }
#pragma unroll
        for (int u = 0; u < 8; ++u) {
            acc.x = fmaf(wv[u], xv[u].x, acc.x);
            acc.y = fmaf(wv[u], xv[u].y, acc.y);
            acc.z = fmaf(wv[u], xv[u].z, acc.z);
            acc.w = fmaf(wv[u], xv[u].w, acc.w);
        }
    }
    for (; j < cnt; ++j) {
        const int   c = sc[j];
        const float w = sv[j];
        const float4 xv = *reinterpret_cast<const float4*>(xb + (size_t)c * N_DIM);
        acc.x = fmaf(w, xv.x, acc.x); acc.y = fmaf(w, xv.y, acc.y);
        acc.z = fmaf(w, xv.z, acc.z); acc.w = fmaf(w, xv.w, acc.w);
    }

    float4* o = reinterpret_cast<float4*>(
        out + ((size_t)b * M_DIM + m) * N_DIM + n0);
    *o = acc;
}

// ---------------------------------------------------------------------------
// kernel_launch: graph-capturable, allocation-free.
// Input order (metadata): 0=x (f32, B*N*K), 1=values (f32, NNZ),
// 2=row_offsets (i32, M+1), 3=column_indices (i32, NNZ). Output f32 B*M*N.
// ---------------------------------------------------------------------------
extern "C" void kernel_launch(void* const* d_in, const int* in_sizes, int n_in,
                              void* d_out, int out_size) {
    const float* x    = (const float*)d_in[0];
    const float* vals = (const float*)d_in[1];
    const int*   roff = (const int*)d_in[2];
    const int*   cidx = (const int*)d_in[3];
    float*       out  = (float*)d_out;

    {
        dim3 block(32, 8, 1);
        dim3 grid(K_DIM / 32, N_DIM / 32, B_DIM);
        transpose_xk<<<grid, block>>>(x);
    }
    {
        dim3 block(256, 1, 1);
        dim3 grid(N_DIM / 1024, M_DIM, B_DIM);
        csr_spmm<<<grid, block>>>(vals, roff, cidx, out);
    }
}